// round 14
// baseline (speedup 1.0000x reference)
#include <cuda_runtime.h>
#include <math.h>
#include <stdint.h>

// ---------------- problem constants ----------------
#define NQ_MAX      20000
#define K3          64
#define INV_RADIUS  (1.0f/0.1125f)
#define DT_F        0.02f

#define MAXFF 3000000
#define MAXFO 1500000

// chunk size for mma scatter
#define KC     32
#define PITCH  36

// ---------------- device scratch ----------------
__device__ __align__(16) float         g_G[122880000];
__device__ __align__(16) float         g_pos2[NQ_MAX * 3];
__device__ __align__(16) float         g_fl[NQ_MAX * 4];
__device__ __align__(16) float         g_x [NQ_MAX * 96];
__device__ __align__(16) float         g_y [NQ_MAX * 64];
__device__ __align__(16) float         g_y2[NQ_MAX * 64];
__device__ __align__(16) float         g_Wt1[64 * 6240];
__device__ __align__(16) float         g_Wt2[64 * 4160];
__device__ int           g_rows_ff[NQ_MAX + 1];
__device__ int           g_rows_fo[NQ_MAX + 1];
__device__ __align__(16) float         g_ew_ff[(size_t)MAXFF * 8];
__device__ unsigned char g_ec_ff[(size_t)MAXFF * 8];
__device__ __align__(16) float         g_ew_fo[(size_t)MAXFO * 8];
__device__ unsigned char g_ec_fo[(size_t)MAXFO * 8];

// ---------------- helpers ----------------
__device__ __forceinline__ float signf(float v) {
    return (v > 0.f) ? 1.f : ((v < 0.f) ? -1.f : 0.f);
}

__device__ __forceinline__ uint32_t f2tf32(float f) {
    uint32_t u;
    asm("cvt.rna.tf32.f32 %0, %1;" : "=r"(u) : "f"(f));
    return u;
}

__device__ __forceinline__ void mma_tf32_16n8k8(float* d, const uint32_t* a,
                                                const uint32_t* b, const float* c)
{
    asm volatile(
        "mma.sync.aligned.m16n8k8.row.col.f32.tf32.tf32.f32 "
        "{%0,%1,%2,%3}, {%4,%5,%6,%7}, {%8,%9}, {%10,%11,%12,%13};"
        : "=f"(d[0]), "=f"(d[1]), "=f"(d[2]), "=f"(d[3])
        : "r"(a[0]), "r"(a[1]), "r"(a[2]), "r"(a[3]),
          "r"(b[0]), "r"(b[1]),
          "f"(c[0]), "f"(c[1]), "f"(c[2]), "f"(c[3]));
}

__device__ void ball_to_cube(float x, float y, float z,
                             float& xq, float& yq, float& zq)
{
    const float eps = 1e-12f;
    float sq   = x*x + y*y + z*z;
    float norm = sqrtf(sq + eps);
    bool  cap  = (1.25f * z * z) > (x*x + y*y);
    float s_cap  = sqrtf(3.f * norm / (norm + fabsf(z) + eps));
    float s_side = norm / sqrtf(x*x + y*y + eps);
    float s  = cap ? s_cap : s_side;
    float xc = x * s;
    float yc = y * s;
    float zc = cap ? (signf(z) * norm) : (1.5f * z);
    if (!(sq > eps)) { xc = 0.f; yc = 0.f; zc = 0.f; }
    float rxy  = sqrtf(xc*xc + yc*yc + eps);
    bool  xbig = fabsf(yc) <= fabsf(xc);
    float dx = (fabsf(xc) > eps) ? xc : 1.0f;
    float dy = (fabsf(yc) > eps) ? yc : 1.0f;
    const float c4pi = 4.0f / 3.14159265358979323846f;
    float tx = signf(xc) * rxy;
    float ty = signf(yc) * rxy;
    float xo = xbig ? tx : (ty * c4pi * atanf(xc / dy));
    float yo = xbig ? (tx * c4pi * atanf(yc / dx)) : ty;
    if (!((xc*xc + yc*yc) > eps)) { xo = 0.f; yo = 0.f; }
    xq = xo; yq = yo; zq = zc;
}

// ---------------- prep kernels ----------------
__global__ void prep_kernel(const float* __restrict__ pos,
                            const float* __restrict__ vel, int n,
                            float* __restrict__ pos2, float* __restrict__ fl)
{
    int i = blockIdx.x * blockDim.x + threadIdx.x;
    if (i >= n) return;
    float vx = vel[i*3+0], vy = vel[i*3+1], vz = vel[i*3+2];
    float v2x = vx;
    float v2y = vy + DT_F * (-9.81f);
    float v2z = vz;
    pos2[i*3+0] = pos[i*3+0] + DT_F * (v2x + vx) * 0.5f;
    pos2[i*3+1] = pos[i*3+1] + DT_F * (v2y + vy) * 0.5f;
    pos2[i*3+2] = pos[i*3+2] + DT_F * (v2z + vz) * 0.5f;
    fl[i*4+0] = 1.f; fl[i*4+1] = v2x; fl[i*4+2] = v2y; fl[i*4+3] = v2z;
}

__global__ void rows_kernel(const int* __restrict__ qidx, int nE, int n,
                            int* __restrict__ rows)
{
    int i = blockIdx.x * blockDim.x + threadIdx.x;
    if (i > n) return;
    int lo = 0, hi = nE;
    while (lo < hi) { int mid = (lo + hi) >> 1; if (qidx[mid] < i) lo = mid + 1; else hi = mid; }
    rows[i] = lo;
}

__global__ void edge_geom_kernel(const float* __restrict__ pq,
                                 const float* __restrict__ ps,
                                 const int* __restrict__ qi,
                                 const int* __restrict__ si, int nE,
                                 float* __restrict__ ew, unsigned char* __restrict__ ec)
{
    int e = blockIdx.x * blockDim.x + threadIdx.x;
    if (e >= nE) return;
    int q = qi[e], s = si[e];
    float dx = (ps[s*3+0] - pq[q*3+0]) * INV_RADIUS;
    float dy = (ps[s*3+1] - pq[q*3+1]) * INV_RADIUS;
    float dz = (ps[s*3+2] - pq[q*3+2]) * INV_RADIUS;
    float r2 = dx*dx + dy*dy + dz*dz;
    float t  = 1.f - r2;
    float win = fminf(fmaxf(t*t*t, 0.f), 1.f);
    float bx, by, bz;
    ball_to_cube(dx, dy, dz, bx, by, bz);
    float gx = (bx + 1.f) * 1.5f, gy = (by + 1.f) * 1.5f, gz = (bz + 1.f) * 1.5f;
    float fx0 = floorf(gx), fy0 = floorf(gy), fz0 = floorf(gz);
    float fx = gx - fx0, fy = gy - fy0, fz = gz - fz0;
    int ix = (int)fx0, iy = (int)fy0, iz = (int)fz0;
#pragma unroll
    for (int c = 0; c < 8; c++) {
        int bxi = (c >> 2) & 1, byi = (c >> 1) & 1, bzi = c & 1;
        float w = (bxi ? fx : 1.f - fx) * (byi ? fy : 1.f - fy) * (bzi ? fz : 1.f - fz);
        int jx = min(max(ix + bxi, 0), 3);
        int jy = min(max(iy + byi, 0), 3);
        int jz = min(max(iz + bzi, 0), 3);
        ew[(size_t)e*8 + c] = win * w;
        ec[(size_t)e*8 + c] = (unsigned char)((jx*4 + jy)*4 + jz);
    }
}

// ---- atomic scatter for small CIN (layer 0) ----
template<int CIN, bool RELU>
__global__ void scatter_kernel(const float* __restrict__ feat,
                               const int* __restrict__ s_idx,
                               const int* __restrict__ rows,
                               const float* __restrict__ ew,
                               const unsigned char* __restrict__ ec,
                               float* __restrict__ G)
{
    constexpr int NJ = (CIN + 31) / 32;
    __shared__ float Gs[K3 * CIN];
    int q = blockIdx.x;
    int tid = threadIdx.x;
    for (int i = tid; i < K3 * CIN; i += blockDim.x) Gs[i] = 0.f;
    __syncthreads();
    int e0 = rows[q], e1 = rows[q + 1];
    int lane = tid & 31, warp = tid >> 5;
    for (int e = e0 + warp; e < e1; e += 8) {
        int s = s_idx[e];
        float sv[NJ];
#pragma unroll
        for (int j = 0; j < NJ; j++) {
            int ci = lane + 32 * j;
            float v = (ci < CIN) ? feat[(size_t)s * CIN + ci] : 0.f;
            if (RELU) v = fmaxf(v, 0.f);
            sv[j] = v;
        }
        float wown = (lane < 8) ? ew[(size_t)e*8 + lane] : 0.f;
        int   cown = (lane < 8) ? (int)ec[(size_t)e*8 + lane] : 0;
#pragma unroll
        for (int c = 0; c < 8; c++) {
            float wc  = __shfl_sync(0xffffffffu, wown, c);
            int  cell = __shfl_sync(0xffffffffu, cown, c);
            if (wc != 0.f) {
#pragma unroll
                for (int j = 0; j < NJ; j++) {
                    int ci = lane + 32 * j;
                    if (ci < CIN) atomicAdd(&Gs[cell * CIN + ci], wc * sv[j]);
                }
            }
        }
    }
    __syncthreads();
    float* go = G + (size_t)q * (K3 * CIN);
    for (int i = tid; i < K3 * CIN; i += blockDim.x) go[i] = Gs[i];
}

// ---- tensor-core scatter: per-query  G[64,CIN] = Wmat(64xE) @ F(ExCIN)  ----
// Wmat built in smem from edge weights (8 unique slots/edge, plain stores).
// FUSE3: instead of writing G, reduce against Wc [64*CIN,3] + dense + integrate.
template<int CIN, bool FUSE3>
__global__ void __launch_bounds__(128)
mma_scatter_kernel(const float* __restrict__ feat,
                   const int* __restrict__ s_idx,
                   const int* __restrict__ rows,
                   const float* __restrict__ ew,
                   const unsigned char* __restrict__ ec,
                   float* __restrict__ G,
                   const float* __restrict__ Wc,
                   const float* __restrict__ Wd,
                   const float* __restrict__ bd,
                   const float* __restrict__ pos2,
                   const float* __restrict__ pos,
                   float* __restrict__ out, int nq)
{
    constexpr int NT = CIN / 8;    // n-tiles
    constexpr int NJ = CIN / 32;
    __shared__ uint32_t Wm[64 * PITCH];
    __shared__ uint32_t Fm[CIN * PITCH];
    __shared__ float red[4][3];

    int q = blockIdx.x;
    if (q >= nq) return;
    int tid  = threadIdx.x;
    int wid  = tid >> 5;
    int lane = tid & 31;

    float acc[NT][4];
#pragma unroll
    for (int nt = 0; nt < NT; nt++)
#pragma unroll
        for (int r = 0; r < 4; r++) acc[nt][r] = 0.f;

    // zero Fm once (stale values are multiplied by zero weights later; must be finite)
    for (int i = tid; i < CIN * PITCH; i += 128) Fm[i] = 0u;

    int e0 = rows[q], e1 = rows[q + 1];

    for (int eb = e0; eb < e1; eb += KC) {
        int ecnt = min(KC, e1 - eb);
        // zero Wm
        for (int i = tid; i < 64 * PITCH; i += 128) Wm[i] = 0u;
        __syncthreads();
        // edge weights -> Wm[cell][e]  (unique slots, plain stores)
        for (int slot = tid; slot < ecnt * 8; slot += 128) {
            int e = slot >> 3, corner = slot & 7;
            float wv = ew[(size_t)(eb + e) * 8 + corner];
            int cell = (int)ec[(size_t)(eb + e) * 8 + corner];
            Wm[cell * PITCH + e] = f2tf32(wv);
        }
        // feature gather -> Fm[ci][e]  (each warp handles 8 edges)
        {
            int sj = 0;
            int mye = eb + wid * 8 + lane;
            if (lane < 8 && mye < e1) sj = s_idx[mye];
#pragma unroll
            for (int j = 0; j < 8; j++) {
                int e = wid * 8 + j;
                if (eb + e >= e1) break;
                int s = __shfl_sync(0xffffffffu, sj, j);
#pragma unroll
                for (int i = 0; i < NJ; i++) {
                    float v = fmaxf(feat[(size_t)s * CIN + lane + 32 * i], 0.f);
                    Fm[(lane + 32 * i) * PITCH + e] = f2tf32(v);
                }
            }
        }
        __syncthreads();
        // MMA: m=64 (4 warps x 16), n=CIN, k=KC (skip empty k-steps)
        int kmax = (ecnt + 7) >> 3;
#pragma unroll
        for (int ks = 0; ks < KC / 8; ks++) {
            if (ks >= kmax) break;
            uint32_t a[4];
            int ra = wid * 16 + (lane >> 2);
            int ca = ks * 8 + (lane & 3);
            a[0] = Wm[ra * PITCH + ca];
            a[1] = Wm[(ra + 8) * PITCH + ca];
            a[2] = Wm[ra * PITCH + ca + 4];
            a[3] = Wm[(ra + 8) * PITCH + ca + 4];
#pragma unroll
            for (int nt = 0; nt < NT; nt++) {
                uint32_t b[2];
                int nb = (nt * 8 + (lane >> 2)) * PITCH + ks * 8 + (lane & 3);
                b[0] = Fm[nb];
                b[1] = Fm[nb + 4];
                mma_tf32_16n8k8(acc[nt], a, b, acc[nt]);
            }
        }
        __syncthreads();
    }

    if (!FUSE3) {
        // write G[q][cell*CIN + ci]
        float* go = G + (size_t)q * (64 * CIN);
        int r = wid * 16 + (lane >> 2);
        int cb = (lane & 3) * 2;
#pragma unroll
        for (int nt = 0; nt < NT; nt++) {
            int c = nt * 8 + cb;
            float2 v0 = make_float2(acc[nt][0], acc[nt][1]);
            float2 v1 = make_float2(acc[nt][2], acc[nt][3]);
            *reinterpret_cast<float2*>(go + r * CIN + c)       = v0;
            *reinterpret_cast<float2*>(go + (r + 8) * CIN + c) = v1;
        }
    } else {
        // layer3: a[n] = sum G[cell,ci] * Wc[(cell*CIN+ci)*3+n]  (+ dense + integrate)
        float a0 = 0.f, a1 = 0.f, a2 = 0.f;
        int r = wid * 16 + (lane >> 2);
        int cb = (lane & 3) * 2;
#pragma unroll
        for (int nt = 0; nt < NT; nt++) {
            int c = nt * 8 + cb;
#pragma unroll
            for (int h = 0; h < 2; h++) {
                int cell = r + h * 8;
                float g0 = acc[nt][h * 2 + 0];
                float g1 = acc[nt][h * 2 + 1];
                const float* w0 = Wc + (size_t)(cell * CIN + c) * 3;
                a0 += g0 * w0[0] + g1 * w0[3];
                a1 += g0 * w0[1] + g1 * w0[4];
                a2 += g0 * w0[2] + g1 * w0[5];
            }
        }
        // dense branch (warp 0 only)
        if (wid == 0) {
#pragma unroll
            for (int i = 0; i < CIN / 32; i++) {
                int k = lane + 32 * i;
                float h = fmaxf(feat[(size_t)q * CIN + k], 0.f);
                a0 += h * Wd[k*3+0]; a1 += h * Wd[k*3+1]; a2 += h * Wd[k*3+2];
            }
        }
#pragma unroll
        for (int off = 16; off > 0; off >>= 1) {
            a0 += __shfl_down_sync(0xffffffffu, a0, off);
            a1 += __shfl_down_sync(0xffffffffu, a1, off);
            a2 += __shfl_down_sync(0xffffffffu, a2, off);
        }
        if (lane == 0) { red[wid][0] = a0; red[wid][1] = a1; red[wid][2] = a2; }
        __syncthreads();
        if (tid == 0) {
            float s0 = red[0][0] + red[1][0] + red[2][0] + red[3][0] + bd[0];
            float s1 = red[0][1] + red[1][1] + red[2][1] + red[3][1] + bd[1];
            float s2 = red[0][2] + red[1][2] + red[2][2] + red[3][2] + bd[2];
            float p0 = pos2[q*3+0] + s0 * (1.f / 128.f);
            float p1 = pos2[q*3+1] + s1 * (1.f / 128.f);
            float p2 = pos2[q*3+2] + s2 * (1.f / 128.f);
            out[q*3+0] = p0;
            out[q*3+1] = p1;
            out[q*3+2] = p2;
            size_t voff = (size_t)nq * 3;
            out[voff + q*3+0] = (p0 - pos[q*3+0]) * (1.f / DT_F);
            out[voff + q*3+1] = (p1 - pos[q*3+1]) * (1.f / DT_F);
            out[voff + q*3+2] = (p2 - pos[q*3+2]) * (1.f / DT_F);
        }
    }
}

// SIMT gemm for small layer-0 matmuls
__global__ void gemm_ep_kernel(int M, int N, int Kmain,
                               const float* __restrict__ A, int lda,
                               const float* __restrict__ B,
                               const float* __restrict__ A2, int lda2, int K2, int relu2,
                               const float* __restrict__ B2,
                               const float* __restrict__ bias,
                               const float* __restrict__ res, int ldres,
                               float* __restrict__ C, int ldc)
{
    const int BMs = 64, BNs = 64, BKs = 16;
    __shared__ float As[BKs][BMs + 4];
    __shared__ float Bs[BKs][BNs + 4];
    int m0  = blockIdx.x * BMs;
    int tid = threadIdx.x;
    int tm = (tid >> 4) * 4;
    int tn = (tid & 15) * 4;
    float acc[4][4];
#pragma unroll
    for (int i = 0; i < 4; i++)
#pragma unroll
        for (int j = 0; j < 4; j++) acc[i][j] = 0.f;

    for (int phase = 0; phase < 2; phase++) {
        const float* Ap; const float* Bp; int K, ldA; bool relu;
        if (phase == 0) { if (Kmain <= 0 || !A) continue; Ap = A;  Bp = B;  K = Kmain; ldA = lda;  relu = false; }
        else            { if (!A2)              continue; Ap = A2; Bp = B2; K = K2;    ldA = lda2; relu = (relu2 != 0); }
        for (int k0 = 0; k0 < K; k0 += BKs) {
            {
                int r  = tid >> 2;
                int kk = (tid & 3) * 4;
                int m  = m0 + r;
                float4 av = make_float4(0.f, 0.f, 0.f, 0.f);
                if (m < M && (k0 + kk) < K)
                    av = *reinterpret_cast<const float4*>(Ap + (size_t)m * ldA + k0 + kk);
                if (relu) {
                    av.x = fmaxf(av.x, 0.f); av.y = fmaxf(av.y, 0.f);
                    av.z = fmaxf(av.z, 0.f); av.w = fmaxf(av.w, 0.f);
                }
                As[kk+0][r] = av.x; As[kk+1][r] = av.y;
                As[kk+2][r] = av.z; As[kk+3][r] = av.w;
            }
            {
                int kb = tid >> 4;
                int nb = (tid & 15) * 4;
                int kg = k0 + kb;
#pragma unroll
                for (int i = 0; i < 4; i++) {
                    float v = 0.f;
                    if (kg < K && (nb + i) < N) v = Bp[(size_t)kg * N + nb + i];
                    Bs[kb][nb + i] = v;
                }
            }
            __syncthreads();
#pragma unroll
            for (int k = 0; k < BKs; k++) {
                float4 a = *reinterpret_cast<const float4*>(&As[k][tm]);
                float4 b = *reinterpret_cast<const float4*>(&Bs[k][tn]);
                acc[0][0] += a.x * b.x; acc[0][1] += a.x * b.y; acc[0][2] += a.x * b.z; acc[0][3] += a.x * b.w;
                acc[1][0] += a.y * b.x; acc[1][1] += a.y * b.y; acc[1][2] += a.y * b.z; acc[1][3] += a.y * b.w;
                acc[2][0] += a.z * b.x; acc[2][1] += a.z * b.y; acc[2][2] += a.z * b.z; acc[2][3] += a.z * b.w;
                acc[3][0] += a.w * b.x; acc[3][1] += a.w * b.y; acc[3][2] += a.w * b.z; acc[3][3] += a.w * b.w;
            }
            __syncthreads();
        }
    }
#pragma unroll
    for (int i = 0; i < 4; i++) {
        int m = m0 + tm + i;
        if (m >= M) continue;
#pragma unroll
        for (int j = 0; j < 4; j++) {
            int nn = tn + j;
            if (nn >= N) continue;
            float v = acc[i][j];
            if (bias) v += bias[nn];
            if (res)  v += res[(size_t)m * ldres + nn];
            C[(size_t)m * ldc + nn] = v;
        }
    }
}

__global__ void concat_wt_kernel(const float* __restrict__ Wc, int Kc,
                                 const float* __restrict__ Wd, int Kd,
                                 float* __restrict__ Wt)
{
    int Kt = Kc + Kd;
    int idx = blockIdx.x * blockDim.x + threadIdx.x;
    if (idx >= 64 * Kt) return;
    int nrow = idx / Kt, k = idx - nrow * Kt;
    Wt[idx] = (k < Kc) ? Wc[(size_t)k * 64 + nrow] : Wd[(size_t)(k - Kc) * 64 + nrow];
}

// -------- mma.sync tf32 GEMM: out[M,64] = [G | relu(X)] @ Wt^T (+bias)(+res) --------
#define TBM 128
#define TBK 16
#define APITCH 24
#define BPITCH 24

template<int KG, int KX, bool RES>
__global__ void __launch_bounds__(256, 1)
mma_gemm_kernel(const float* __restrict__ G,
                const float* __restrict__ X,
                const float* __restrict__ Wt,
                const float* __restrict__ bias,
                const float* __restrict__ res,
                float* __restrict__ out, int M)
{
    constexpr int KT = KG + KX;
    constexpr int NITER = KT / TBK;

    __shared__ uint32_t As[TBM * APITCH];
    __shared__ uint32_t Bs[64 * BPITCH];

    int tid  = threadIdx.x;
    int wid  = tid >> 5;
    int lane = tid & 31;
    int wm   = wid >> 1;
    int wn   = wid & 1;
    int m0   = blockIdx.x * TBM;

    float acc[2][4][4];
#pragma unroll
    for (int mt = 0; mt < 2; mt++)
#pragma unroll
        for (int nt = 0; nt < 4; nt++)
#pragma unroll
            for (int r = 0; r < 4; r++) acc[mt][nt][r] = 0.f;

    int brow = tid >> 2;
    int bk4  = (tid & 3) << 2;

    float4 pa0, pa1, pb;

    auto ldA = [&](int it, int j) -> float4 {
        int g   = j * 256 + tid;
        int row = g >> 2;
        int k   = it * TBK + ((g & 3) << 2);
        int m   = m0 + row;
        float4 v = make_float4(0.f, 0.f, 0.f, 0.f);
        if (m < M) {
            if (k < KG) {
                v = *reinterpret_cast<const float4*>(G + (size_t)m * KG + k);
            } else if (KX > 0) {
                v = *reinterpret_cast<const float4*>(X + (size_t)m * KX + (k - KG));
                v.x = fmaxf(v.x, 0.f); v.y = fmaxf(v.y, 0.f);
                v.z = fmaxf(v.z, 0.f); v.w = fmaxf(v.w, 0.f);
            }
        }
        return v;
    };
    auto ldB = [&](int it) -> float4 {
        int k = it * TBK + bk4;
        return *reinterpret_cast<const float4*>(Wt + (size_t)brow * KT + k);
    };

    pa0 = ldA(0, 0); pa1 = ldA(0, 1); pb = ldB(0);

    for (int it = 0; it < NITER; it++) {
        {
            int g0  = tid;
            int r0  = g0 >> 2;
            uint4 u0 = make_uint4(f2tf32(pa0.x), f2tf32(pa0.y), f2tf32(pa0.z), f2tf32(pa0.w));
            *reinterpret_cast<uint4*>(&As[r0 * APITCH + ((g0 & 3) << 2)]) = u0;
            int g1  = 256 + tid;
            int r1  = g1 >> 2;
            uint4 u1 = make_uint4(f2tf32(pa1.x), f2tf32(pa1.y), f2tf32(pa1.z), f2tf32(pa1.w));
            *reinterpret_cast<uint4*>(&As[r1 * APITCH + ((g1 & 3) << 2)]) = u1;
            uint4 ub = make_uint4(f2tf32(pb.x), f2tf32(pb.y), f2tf32(pb.z), f2tf32(pb.w));
            *reinterpret_cast<uint4*>(&Bs[brow * BPITCH + bk4]) = ub;
        }
        __syncthreads();

        if (it + 1 < NITER) {
            pa0 = ldA(it + 1, 0); pa1 = ldA(it + 1, 1); pb = ldB(it + 1);
        }

#pragma unroll
        for (int ks = 0; ks < 2; ks++) {
            uint32_t af[2][4];
#pragma unroll
            for (int mt = 0; mt < 2; mt++) {
                int ra = wm * 32 + mt * 16 + (lane >> 2);
                int ca = ks * 8 + (lane & 3);
                af[mt][0] = As[ra * APITCH + ca];
                af[mt][1] = As[(ra + 8) * APITCH + ca];
                af[mt][2] = As[ra * APITCH + ca + 4];
                af[mt][3] = As[(ra + 8) * APITCH + ca + 4];
            }
            uint32_t bf[4][2];
#pragma unroll
            for (int nt = 0; nt < 4; nt++) {
                int cn = wn * 32 + nt * 8 + (lane >> 2);
                int rk = ks * 8 + (lane & 3);
                bf[nt][0] = Bs[cn * BPITCH + rk];
                bf[nt][1] = Bs[cn * BPITCH + rk + 4];
            }
#pragma unroll
            for (int mt = 0; mt < 2; mt++)
#pragma unroll
                for (int nt = 0; nt < 4; nt++)
                    mma_tf32_16n8k8(acc[mt][nt], af[mt], bf[nt], acc[mt][nt]);
        }
        __syncthreads();
    }

#pragma unroll
    for (int mt = 0; mt < 2; mt++) {
#pragma unroll
        for (int r2 = 0; r2 < 2; r2++) {
            int m = m0 + wm * 32 + mt * 16 + (lane >> 2) + r2 * 8;
            if (m >= M) continue;
#pragma unroll
            for (int nt = 0; nt < 4; nt++) {
                int c = wn * 32 + nt * 8 + (lane & 3) * 2;
                float v0 = acc[mt][nt][r2 * 2 + 0] + bias[c];
                float v1 = acc[mt][nt][r2 * 2 + 1] + bias[c + 1];
                if (RES) {
                    v0 += res[(size_t)m * 64 + c];
                    v1 += res[(size_t)m * 64 + c + 1];
                }
                out[(size_t)m * 64 + c]     = v0;
                out[(size_t)m * 64 + c + 1] = v1;
            }
        }
    }
}

// ---------------- launcher ----------------
extern "C" void kernel_launch(void* const* d_in, const int* in_sizes, int n_in,
                              void* d_out, int out_size)
{
    const float* pos       = (const float*)d_in[0];
    const float* vel       = (const float*)d_in[1];
    const float* box       = (const float*)d_in[2];
    const float* box_feats = (const float*)d_in[3];
    const int*   ff_q      = (const int*)d_in[4];
    const int*   ff_s      = (const int*)d_in[5];
    const int*   fo_q      = (const int*)d_in[6];
    const int*   fo_s      = (const int*)d_in[7];
    const float* w_cf0     = (const float*)d_in[8];
    const float* w_co0     = (const float*)d_in[9];
    const float* w_d0      = (const float*)d_in[10];
    const float* b_d0      = (const float*)d_in[11];
    const float* w_c1      = (const float*)d_in[12];
    const float* w_d1      = (const float*)d_in[13];
    const float* b_d1      = (const float*)d_in[14];
    const float* w_c2      = (const float*)d_in[15];
    const float* w_d2      = (const float*)d_in[16];
    const float* b_d2      = (const float*)d_in[17];
    const float* w_c3      = (const float*)d_in[18];
    const float* w_d3      = (const float*)d_in[19];
    const float* b_d3      = (const float*)d_in[20];

    int n    = in_sizes[0] / 3;
    int nEff = in_sizes[4];
    int nEfo = in_sizes[6];
    float* out = (float*)d_out;

    float *G, *pos2, *fl, *x, *y, *y2, *ewff, *ewfo, *Wt1, *Wt2;
    int *rows_ff, *rows_fo;
    unsigned char *ecff, *ecfo;
    cudaGetSymbolAddress((void**)&G,       g_G);
    cudaGetSymbolAddress((void**)&pos2,    g_pos2);
    cudaGetSymbolAddress((void**)&fl,      g_fl);
    cudaGetSymbolAddress((void**)&x,       g_x);
    cudaGetSymbolAddress((void**)&y,       g_y);
    cudaGetSymbolAddress((void**)&y2,      g_y2);
    cudaGetSymbolAddress((void**)&Wt1,     g_Wt1);
    cudaGetSymbolAddress((void**)&Wt2,     g_Wt2);
    cudaGetSymbolAddress((void**)&rows_ff, g_rows_ff);
    cudaGetSymbolAddress((void**)&rows_fo, g_rows_fo);
    cudaGetSymbolAddress((void**)&ewff,    g_ew_ff);
    cudaGetSymbolAddress((void**)&ecff,    g_ec_ff);
    cudaGetSymbolAddress((void**)&ewfo,    g_ew_fo);
    cudaGetSymbolAddress((void**)&ecfo,    g_ec_fo);

    int gb  = (n + 63) / 64;
    int gtc = (n + 127) / 128;

    prep_kernel<<<(n + 255) / 256, 256>>>(pos, vel, n, pos2, fl);
    rows_kernel<<<(n + 256) / 256, 256>>>(ff_q, nEff, n, rows_ff);
    rows_kernel<<<(n + 256) / 256, 256>>>(fo_q, nEfo, n, rows_fo);
    edge_geom_kernel<<<(nEff + 255) / 256, 256>>>(pos2, pos2, ff_q, ff_s, nEff, ewff, ecff);
    edge_geom_kernel<<<(nEfo + 255) / 256, 256>>>(pos2, box,  fo_q, fo_s, nEfo, ewfo, ecfo);

    concat_wt_kernel<<<(64 * 6240 + 255) / 256, 256>>>(w_c1, 6144, w_d1, 96, Wt1);
    concat_wt_kernel<<<(64 * 4160 + 255) / 256, 256>>>(w_c2, 4096, w_d2, 64, Wt2);

    // ---- layer 0 (atomic scatter + SIMT gemms) ----
    scatter_kernel<3, false><<<n, 256>>>(box_feats, fo_s, rows_fo, ewfo, ecfo, G);
    gemm_ep_kernel<<<gb, 256>>>(n, 32, 192, G, 192, w_co0,
                                nullptr, 0, 0, 0, nullptr,
                                nullptr, nullptr, 0, x + 0, 96);
    scatter_kernel<4, false><<<n, 256>>>(fl, ff_s, rows_ff, ewff, ecff, G);
    gemm_ep_kernel<<<gb, 256>>>(n, 32, 256, G, 256, w_cf0,
                                nullptr, 0, 0, 0, nullptr,
                                nullptr, nullptr, 0, x + 32, 96);
    gemm_ep_kernel<<<gb, 256>>>(n, 32, 0, nullptr, 0, nullptr,
                                fl, 4, 4, 0, w_d0,
                                b_d0, nullptr, 0, x + 64, 96);

    // ---- layer 1: tensor-core scatter + tensor-core GEMM ----
    mma_scatter_kernel<96, false><<<n, 128>>>(x, ff_s, rows_ff, ewff, ecff, G,
                                              nullptr, nullptr, nullptr,
                                              nullptr, nullptr, nullptr, n);
    mma_gemm_kernel<6144, 96, false><<<gtc, 256>>>(G, x, Wt1, b_d1, nullptr, y, n);

    // ---- layer 2 ----
    mma_scatter_kernel<64, false><<<n, 128>>>(y, ff_s, rows_ff, ewff, ecff, G,
                                              nullptr, nullptr, nullptr,
                                              nullptr, nullptr, nullptr, n);
    mma_gemm_kernel<4096, 64, true><<<gtc, 256>>>(G, y, Wt2, b_d2, y, y2, n);

    // ---- layer 3: fused scatter + reduce + integration ----
    mma_scatter_kernel<64, true><<<n, 128>>>(y2, ff_s, rows_ff, ewff, ecff, nullptr,
                                             w_c3, w_d3, b_d3, pos2, pos, out, n);
}

// round 15
// speedup vs baseline: 1.0013x; 1.0013x over previous
#include <cuda_runtime.h>
#include <math.h>
#include <stdint.h>

// ---------------- problem constants ----------------
#define NQ_MAX      20000
#define K3          64
#define INV_RADIUS  (1.0f/0.1125f)
#define DT_F        0.02f

#define MAXFF 3000000
#define MAXFO 1500000

// chunk size for mma scatter
#define KC     32
#define PITCH  36

// ---------------- device scratch ----------------
__device__ __align__(16) float         g_G[122880000];
__device__ __align__(16) float         g_pos2[NQ_MAX * 3];
__device__ __align__(16) float         g_fl[NQ_MAX * 4];
__device__ __align__(16) float         g_x [NQ_MAX * 96];
__device__ __align__(16) float         g_y [NQ_MAX * 64];
__device__ __align__(16) float         g_y2[NQ_MAX * 64];
__device__ __align__(16) float         g_Wt1[64 * 6240];
__device__ __align__(16) float         g_Wt2[64 * 4160];
__device__ int           g_rows_ff[NQ_MAX + 1];
__device__ int           g_rows_fo[NQ_MAX + 1];
__device__ __align__(16) float         g_ew_ff[(size_t)MAXFF * 8];
__device__ unsigned char g_ec_ff[(size_t)MAXFF * 8];
__device__ __align__(16) float         g_ew_fo[(size_t)MAXFO * 8];
__device__ unsigned char g_ec_fo[(size_t)MAXFO * 8];

// ---------------- helpers ----------------
__device__ __forceinline__ float signf(float v) {
    return (v > 0.f) ? 1.f : ((v < 0.f) ? -1.f : 0.f);
}

__device__ __forceinline__ uint32_t f2tf32(float f) {
    uint32_t u;
    asm("cvt.rna.tf32.f32 %0, %1;" : "=r"(u) : "f"(f));
    return u;
}

__device__ __forceinline__ void mma_tf32_16n8k8(float* d, const uint32_t* a,
                                                const uint32_t* b, const float* c)
{
    asm volatile(
        "mma.sync.aligned.m16n8k8.row.col.f32.tf32.tf32.f32 "
        "{%0,%1,%2,%3}, {%4,%5,%6,%7}, {%8,%9}, {%10,%11,%12,%13};"
        : "=f"(d[0]), "=f"(d[1]), "=f"(d[2]), "=f"(d[3])
        : "r"(a[0]), "r"(a[1]), "r"(a[2]), "r"(a[3]),
          "r"(b[0]), "r"(b[1]),
          "f"(c[0]), "f"(c[1]), "f"(c[2]), "f"(c[3]));
}

__device__ void ball_to_cube(float x, float y, float z,
                             float& xq, float& yq, float& zq)
{
    const float eps = 1e-12f;
    float sq   = x*x + y*y + z*z;
    float norm = sqrtf(sq + eps);
    bool  cap  = (1.25f * z * z) > (x*x + y*y);
    float s_cap  = sqrtf(3.f * norm / (norm + fabsf(z) + eps));
    float s_side = norm / sqrtf(x*x + y*y + eps);
    float s  = cap ? s_cap : s_side;
    float xc = x * s;
    float yc = y * s;
    float zc = cap ? (signf(z) * norm) : (1.5f * z);
    if (!(sq > eps)) { xc = 0.f; yc = 0.f; zc = 0.f; }
    float rxy  = sqrtf(xc*xc + yc*yc + eps);
    bool  xbig = fabsf(yc) <= fabsf(xc);
    float dx = (fabsf(xc) > eps) ? xc : 1.0f;
    float dy = (fabsf(yc) > eps) ? yc : 1.0f;
    const float c4pi = 4.0f / 3.14159265358979323846f;
    float tx = signf(xc) * rxy;
    float ty = signf(yc) * rxy;
    float xo = xbig ? tx : (ty * c4pi * atanf(xc / dy));
    float yo = xbig ? (tx * c4pi * atanf(yc / dx)) : ty;
    if (!((xc*xc + yc*yc) > eps)) { xo = 0.f; yo = 0.f; }
    xq = xo; yq = yo; zq = zc;
}

// ---------------- prep kernels ----------------
__global__ void prep_kernel(const float* __restrict__ pos,
                            const float* __restrict__ vel, int n,
                            float* __restrict__ pos2, float* __restrict__ fl)
{
    int i = blockIdx.x * blockDim.x + threadIdx.x;
    if (i >= n) return;
    float vx = vel[i*3+0], vy = vel[i*3+1], vz = vel[i*3+2];
    float v2x = vx;
    float v2y = vy + DT_F * (-9.81f);
    float v2z = vz;
    pos2[i*3+0] = pos[i*3+0] + DT_F * (v2x + vx) * 0.5f;
    pos2[i*3+1] = pos[i*3+1] + DT_F * (v2y + vy) * 0.5f;
    pos2[i*3+2] = pos[i*3+2] + DT_F * (v2z + vz) * 0.5f;
    fl[i*4+0] = 1.f; fl[i*4+1] = v2x; fl[i*4+2] = v2y; fl[i*4+3] = v2z;
}

__global__ void rows_kernel(const int* __restrict__ qidx, int nE, int n,
                            int* __restrict__ rows)
{
    int i = blockIdx.x * blockDim.x + threadIdx.x;
    if (i > n) return;
    int lo = 0, hi = nE;
    while (lo < hi) { int mid = (lo + hi) >> 1; if (qidx[mid] < i) lo = mid + 1; else hi = mid; }
    rows[i] = lo;
}

__global__ void edge_geom_kernel(const float* __restrict__ pq,
                                 const float* __restrict__ ps,
                                 const int* __restrict__ qi,
                                 const int* __restrict__ si, int nE,
                                 float* __restrict__ ew, unsigned char* __restrict__ ec)
{
    int e = blockIdx.x * blockDim.x + threadIdx.x;
    if (e >= nE) return;
    int q = qi[e], s = si[e];
    float dx = (ps[s*3+0] - pq[q*3+0]) * INV_RADIUS;
    float dy = (ps[s*3+1] - pq[q*3+1]) * INV_RADIUS;
    float dz = (ps[s*3+2] - pq[q*3+2]) * INV_RADIUS;
    float r2 = dx*dx + dy*dy + dz*dz;
    float t  = 1.f - r2;
    float win = fminf(fmaxf(t*t*t, 0.f), 1.f);
    float bx, by, bz;
    ball_to_cube(dx, dy, dz, bx, by, bz);
    float gx = (bx + 1.f) * 1.5f, gy = (by + 1.f) * 1.5f, gz = (bz + 1.f) * 1.5f;
    float fx0 = floorf(gx), fy0 = floorf(gy), fz0 = floorf(gz);
    float fx = gx - fx0, fy = gy - fy0, fz = gz - fz0;
    int ix = (int)fx0, iy = (int)fy0, iz = (int)fz0;
#pragma unroll
    for (int c = 0; c < 8; c++) {
        int bxi = (c >> 2) & 1, byi = (c >> 1) & 1, bzi = c & 1;
        float w = (bxi ? fx : 1.f - fx) * (byi ? fy : 1.f - fy) * (bzi ? fz : 1.f - fz);
        int jx = min(max(ix + bxi, 0), 3);
        int jy = min(max(iy + byi, 0), 3);
        int jz = min(max(iz + bzi, 0), 3);
        ew[(size_t)e*8 + c] = win * w;
        ec[(size_t)e*8 + c] = (unsigned char)((jx*4 + jy)*4 + jz);
    }
}

// ---- atomic scatter for small CIN (layer 0) ----
template<int CIN, bool RELU>
__global__ void scatter_kernel(const float* __restrict__ feat,
                               const int* __restrict__ s_idx,
                               const int* __restrict__ rows,
                               const float* __restrict__ ew,
                               const unsigned char* __restrict__ ec,
                               float* __restrict__ G)
{
    constexpr int NJ = (CIN + 31) / 32;
    __shared__ float Gs[K3 * CIN];
    int q = blockIdx.x;
    int tid = threadIdx.x;
    for (int i = tid; i < K3 * CIN; i += blockDim.x) Gs[i] = 0.f;
    __syncthreads();
    int e0 = rows[q], e1 = rows[q + 1];
    int lane = tid & 31, warp = tid >> 5;
    for (int e = e0 + warp; e < e1; e += 8) {
        int s = s_idx[e];
        float sv[NJ];
#pragma unroll
        for (int j = 0; j < NJ; j++) {
            int ci = lane + 32 * j;
            float v = (ci < CIN) ? feat[(size_t)s * CIN + ci] : 0.f;
            if (RELU) v = fmaxf(v, 0.f);
            sv[j] = v;
        }
        float wown = (lane < 8) ? ew[(size_t)e*8 + lane] : 0.f;
        int   cown = (lane < 8) ? (int)ec[(size_t)e*8 + lane] : 0;
#pragma unroll
        for (int c = 0; c < 8; c++) {
            float wc  = __shfl_sync(0xffffffffu, wown, c);
            int  cell = __shfl_sync(0xffffffffu, cown, c);
            if (wc != 0.f) {
#pragma unroll
                for (int j = 0; j < NJ; j++) {
                    int ci = lane + 32 * j;
                    if (ci < CIN) atomicAdd(&Gs[cell * CIN + ci], wc * sv[j]);
                }
            }
        }
    }
    __syncthreads();
    float* go = G + (size_t)q * (K3 * CIN);
    for (int i = tid; i < K3 * CIN; i += blockDim.x) go[i] = Gs[i];
}

// ---- tensor-core scatter: per-query  G[64,CIN] = Wmat(64xE) @ F(ExCIN)  ----
// Wmat built in smem from edge weights (8 unique slots/edge, plain stores).
// FUSE3: instead of writing G, reduce against Wc [64*CIN,3] + dense + integrate.
template<int CIN, bool FUSE3>
__global__ void __launch_bounds__(128)
mma_scatter_kernel(const float* __restrict__ feat,
                   const int* __restrict__ s_idx,
                   const int* __restrict__ rows,
                   const float* __restrict__ ew,
                   const unsigned char* __restrict__ ec,
                   float* __restrict__ G,
                   const float* __restrict__ Wc,
                   const float* __restrict__ Wd,
                   const float* __restrict__ bd,
                   const float* __restrict__ pos2,
                   const float* __restrict__ pos,
                   float* __restrict__ out, int nq)
{
    constexpr int NT = CIN / 8;    // n-tiles
    constexpr int NJ = CIN / 32;
    __shared__ uint32_t Wm[64 * PITCH];
    __shared__ uint32_t Fm[CIN * PITCH];
    __shared__ float red[4][3];

    int q = blockIdx.x;
    if (q >= nq) return;
    int tid  = threadIdx.x;
    int wid  = tid >> 5;
    int lane = tid & 31;

    float acc[NT][4];
#pragma unroll
    for (int nt = 0; nt < NT; nt++)
#pragma unroll
        for (int r = 0; r < 4; r++) acc[nt][r] = 0.f;

    // zero Fm once (stale values are multiplied by zero weights later; must be finite)
    for (int i = tid; i < CIN * PITCH; i += 128) Fm[i] = 0u;

    int e0 = rows[q], e1 = rows[q + 1];

    for (int eb = e0; eb < e1; eb += KC) {
        int ecnt = min(KC, e1 - eb);
        // zero Wm
        for (int i = tid; i < 64 * PITCH; i += 128) Wm[i] = 0u;
        __syncthreads();
        // edge weights -> Wm[cell][e]  (unique slots, plain stores)
        for (int slot = tid; slot < ecnt * 8; slot += 128) {
            int e = slot >> 3, corner = slot & 7;
            float wv = ew[(size_t)(eb + e) * 8 + corner];
            int cell = (int)ec[(size_t)(eb + e) * 8 + corner];
            Wm[cell * PITCH + e] = f2tf32(wv);
        }
        // feature gather -> Fm[ci][e]  (each warp handles 8 edges)
        {
            int sj = 0;
            int mye = eb + wid * 8 + lane;
            if (lane < 8 && mye < e1) sj = s_idx[mye];
#pragma unroll
            for (int j = 0; j < 8; j++) {
                int e = wid * 8 + j;
                if (eb + e >= e1) break;
                int s = __shfl_sync(0xffffffffu, sj, j);
#pragma unroll
                for (int i = 0; i < NJ; i++) {
                    float v = fmaxf(feat[(size_t)s * CIN + lane + 32 * i], 0.f);
                    Fm[(lane + 32 * i) * PITCH + e] = f2tf32(v);
                }
            }
        }
        __syncthreads();
        // MMA: m=64 (4 warps x 16), n=CIN, k=KC (skip empty k-steps)
        int kmax = (ecnt + 7) >> 3;
#pragma unroll
        for (int ks = 0; ks < KC / 8; ks++) {
            if (ks >= kmax) break;
            uint32_t a[4];
            int ra = wid * 16 + (lane >> 2);
            int ca = ks * 8 + (lane & 3);
            a[0] = Wm[ra * PITCH + ca];
            a[1] = Wm[(ra + 8) * PITCH + ca];
            a[2] = Wm[ra * PITCH + ca + 4];
            a[3] = Wm[(ra + 8) * PITCH + ca + 4];
#pragma unroll
            for (int nt = 0; nt < NT; nt++) {
                uint32_t b[2];
                int nb = (nt * 8 + (lane >> 2)) * PITCH + ks * 8 + (lane & 3);
                b[0] = Fm[nb];
                b[1] = Fm[nb + 4];
                mma_tf32_16n8k8(acc[nt], a, b, acc[nt]);
            }
        }
        __syncthreads();
    }

    if (!FUSE3) {
        // write G[q][cell*CIN + ci]
        float* go = G + (size_t)q * (64 * CIN);
        int r = wid * 16 + (lane >> 2);
        int cb = (lane & 3) * 2;
#pragma unroll
        for (int nt = 0; nt < NT; nt++) {
            int c = nt * 8 + cb;
            float2 v0 = make_float2(acc[nt][0], acc[nt][1]);
            float2 v1 = make_float2(acc[nt][2], acc[nt][3]);
            *reinterpret_cast<float2*>(go + r * CIN + c)       = v0;
            *reinterpret_cast<float2*>(go + (r + 8) * CIN + c) = v1;
        }
    } else {
        // layer3: a[n] = sum G[cell,ci] * Wc[(cell*CIN+ci)*3+n]  (+ dense + integrate)
        float a0 = 0.f, a1 = 0.f, a2 = 0.f;
        int r = wid * 16 + (lane >> 2);
        int cb = (lane & 3) * 2;
#pragma unroll
        for (int nt = 0; nt < NT; nt++) {
            int c = nt * 8 + cb;
#pragma unroll
            for (int h = 0; h < 2; h++) {
                int cell = r + h * 8;
                float g0 = acc[nt][h * 2 + 0];
                float g1 = acc[nt][h * 2 + 1];
                const float* w0 = Wc + (size_t)(cell * CIN + c) * 3;
                a0 += g0 * w0[0] + g1 * w0[3];
                a1 += g0 * w0[1] + g1 * w0[4];
                a2 += g0 * w0[2] + g1 * w0[5];
            }
        }
        // dense branch (warp 0 only)
        if (wid == 0) {
#pragma unroll
            for (int i = 0; i < CIN / 32; i++) {
                int k = lane + 32 * i;
                float h = fmaxf(feat[(size_t)q * CIN + k], 0.f);
                a0 += h * Wd[k*3+0]; a1 += h * Wd[k*3+1]; a2 += h * Wd[k*3+2];
            }
        }
#pragma unroll
        for (int off = 16; off > 0; off >>= 1) {
            a0 += __shfl_down_sync(0xffffffffu, a0, off);
            a1 += __shfl_down_sync(0xffffffffu, a1, off);
            a2 += __shfl_down_sync(0xffffffffu, a2, off);
        }
        if (lane == 0) { red[wid][0] = a0; red[wid][1] = a1; red[wid][2] = a2; }
        __syncthreads();
        if (tid == 0) {
            float s0 = red[0][0] + red[1][0] + red[2][0] + red[3][0] + bd[0];
            float s1 = red[0][1] + red[1][1] + red[2][1] + red[3][1] + bd[1];
            float s2 = red[0][2] + red[1][2] + red[2][2] + red[3][2] + bd[2];
            float p0 = pos2[q*3+0] + s0 * (1.f / 128.f);
            float p1 = pos2[q*3+1] + s1 * (1.f / 128.f);
            float p2 = pos2[q*3+2] + s2 * (1.f / 128.f);
            out[q*3+0] = p0;
            out[q*3+1] = p1;
            out[q*3+2] = p2;
            size_t voff = (size_t)nq * 3;
            out[voff + q*3+0] = (p0 - pos[q*3+0]) * (1.f / DT_F);
            out[voff + q*3+1] = (p1 - pos[q*3+1]) * (1.f / DT_F);
            out[voff + q*3+2] = (p2 - pos[q*3+2]) * (1.f / DT_F);
        }
    }
}

// SIMT gemm for small layer-0 matmuls
__global__ void gemm_ep_kernel(int M, int N, int Kmain,
                               const float* __restrict__ A, int lda,
                               const float* __restrict__ B,
                               const float* __restrict__ A2, int lda2, int K2, int relu2,
                               const float* __restrict__ B2,
                               const float* __restrict__ bias,
                               const float* __restrict__ res, int ldres,
                               float* __restrict__ C, int ldc)
{
    const int BMs = 64, BNs = 64, BKs = 16;
    __shared__ float As[BKs][BMs + 4];
    __shared__ float Bs[BKs][BNs + 4];
    int m0  = blockIdx.x * BMs;
    int tid = threadIdx.x;
    int tm = (tid >> 4) * 4;
    int tn = (tid & 15) * 4;
    float acc[4][4];
#pragma unroll
    for (int i = 0; i < 4; i++)
#pragma unroll
        for (int j = 0; j < 4; j++) acc[i][j] = 0.f;

    for (int phase = 0; phase < 2; phase++) {
        const float* Ap; const float* Bp; int K, ldA; bool relu;
        if (phase == 0) { if (Kmain <= 0 || !A) continue; Ap = A;  Bp = B;  K = Kmain; ldA = lda;  relu = false; }
        else            { if (!A2)              continue; Ap = A2; Bp = B2; K = K2;    ldA = lda2; relu = (relu2 != 0); }
        for (int k0 = 0; k0 < K; k0 += BKs) {
            {
                int r  = tid >> 2;
                int kk = (tid & 3) * 4;
                int m  = m0 + r;
                float4 av = make_float4(0.f, 0.f, 0.f, 0.f);
                if (m < M && (k0 + kk) < K)
                    av = *reinterpret_cast<const float4*>(Ap + (size_t)m * ldA + k0 + kk);
                if (relu) {
                    av.x = fmaxf(av.x, 0.f); av.y = fmaxf(av.y, 0.f);
                    av.z = fmaxf(av.z, 0.f); av.w = fmaxf(av.w, 0.f);
                }
                As[kk+0][r] = av.x; As[kk+1][r] = av.y;
                As[kk+2][r] = av.z; As[kk+3][r] = av.w;
            }
            {
                int kb = tid >> 4;
                int nb = (tid & 15) * 4;
                int kg = k0 + kb;
#pragma unroll
                for (int i = 0; i < 4; i++) {
                    float v = 0.f;
                    if (kg < K && (nb + i) < N) v = Bp[(size_t)kg * N + nb + i];
                    Bs[kb][nb + i] = v;
                }
            }
            __syncthreads();
#pragma unroll
            for (int k = 0; k < BKs; k++) {
                float4 a = *reinterpret_cast<const float4*>(&As[k][tm]);
                float4 b = *reinterpret_cast<const float4*>(&Bs[k][tn]);
                acc[0][0] += a.x * b.x; acc[0][1] += a.x * b.y; acc[0][2] += a.x * b.z; acc[0][3] += a.x * b.w;
                acc[1][0] += a.y * b.x; acc[1][1] += a.y * b.y; acc[1][2] += a.y * b.z; acc[1][3] += a.y * b.w;
                acc[2][0] += a.z * b.x; acc[2][1] += a.z * b.y; acc[2][2] += a.z * b.z; acc[2][3] += a.z * b.w;
                acc[3][0] += a.w * b.x; acc[3][1] += a.w * b.y; acc[3][2] += a.w * b.z; acc[3][3] += a.w * b.w;
            }
            __syncthreads();
        }
    }
#pragma unroll
    for (int i = 0; i < 4; i++) {
        int m = m0 + tm + i;
        if (m >= M) continue;
#pragma unroll
        for (int j = 0; j < 4; j++) {
            int nn = tn + j;
            if (nn >= N) continue;
            float v = acc[i][j];
            if (bias) v += bias[nn];
            if (res)  v += res[(size_t)m * ldres + nn];
            C[(size_t)m * ldc + nn] = v;
        }
    }
}

__global__ void concat_wt_kernel(const float* __restrict__ Wc, int Kc,
                                 const float* __restrict__ Wd, int Kd,
                                 float* __restrict__ Wt)
{
    int Kt = Kc + Kd;
    int idx = blockIdx.x * blockDim.x + threadIdx.x;
    if (idx >= 64 * Kt) return;
    int nrow = idx / Kt, k = idx - nrow * Kt;
    Wt[idx] = (k < Kc) ? Wc[(size_t)k * 64 + nrow] : Wd[(size_t)(k - Kc) * 64 + nrow];
}

// -------- mma.sync tf32 GEMM: out[M,64] = [G | relu(X)] @ Wt^T (+bias)(+res) --------
#define TBM 128
#define TBK 16
#define APITCH 24
#define BPITCH 24

template<int KG, int KX, bool RES>
__global__ void __launch_bounds__(256, 1)
mma_gemm_kernel(const float* __restrict__ G,
                const float* __restrict__ X,
                const float* __restrict__ Wt,
                const float* __restrict__ bias,
                const float* __restrict__ res,
                float* __restrict__ out, int M)
{
    constexpr int KT = KG + KX;
    constexpr int NITER = KT / TBK;

    __shared__ uint32_t As[TBM * APITCH];
    __shared__ uint32_t Bs[64 * BPITCH];

    int tid  = threadIdx.x;
    int wid  = tid >> 5;
    int lane = tid & 31;
    int wm   = wid >> 1;
    int wn   = wid & 1;
    int m0   = blockIdx.x * TBM;

    float acc[2][4][4];
#pragma unroll
    for (int mt = 0; mt < 2; mt++)
#pragma unroll
        for (int nt = 0; nt < 4; nt++)
#pragma unroll
            for (int r = 0; r < 4; r++) acc[mt][nt][r] = 0.f;

    int brow = tid >> 2;
    int bk4  = (tid & 3) << 2;

    float4 pa0, pa1, pb;

    auto ldA = [&](int it, int j) -> float4 {
        int g   = j * 256 + tid;
        int row = g >> 2;
        int k   = it * TBK + ((g & 3) << 2);
        int m   = m0 + row;
        float4 v = make_float4(0.f, 0.f, 0.f, 0.f);
        if (m < M) {
            if (k < KG) {
                v = *reinterpret_cast<const float4*>(G + (size_t)m * KG + k);
            } else if (KX > 0) {
                v = *reinterpret_cast<const float4*>(X + (size_t)m * KX + (k - KG));
                v.x = fmaxf(v.x, 0.f); v.y = fmaxf(v.y, 0.f);
                v.z = fmaxf(v.z, 0.f); v.w = fmaxf(v.w, 0.f);
            }
        }
        return v;
    };
    auto ldB = [&](int it) -> float4 {
        int k = it * TBK + bk4;
        return *reinterpret_cast<const float4*>(Wt + (size_t)brow * KT + k);
    };

    pa0 = ldA(0, 0); pa1 = ldA(0, 1); pb = ldB(0);

    for (int it = 0; it < NITER; it++) {
        {
            int g0  = tid;
            int r0  = g0 >> 2;
            uint4 u0 = make_uint4(f2tf32(pa0.x), f2tf32(pa0.y), f2tf32(pa0.z), f2tf32(pa0.w));
            *reinterpret_cast<uint4*>(&As[r0 * APITCH + ((g0 & 3) << 2)]) = u0;
            int g1  = 256 + tid;
            int r1  = g1 >> 2;
            uint4 u1 = make_uint4(f2tf32(pa1.x), f2tf32(pa1.y), f2tf32(pa1.z), f2tf32(pa1.w));
            *reinterpret_cast<uint4*>(&As[r1 * APITCH + ((g1 & 3) << 2)]) = u1;
            uint4 ub = make_uint4(f2tf32(pb.x), f2tf32(pb.y), f2tf32(pb.z), f2tf32(pb.w));
            *reinterpret_cast<uint4*>(&Bs[brow * BPITCH + bk4]) = ub;
        }
        __syncthreads();

        if (it + 1 < NITER) {
            pa0 = ldA(it + 1, 0); pa1 = ldA(it + 1, 1); pb = ldB(it + 1);
        }

#pragma unroll
        for (int ks = 0; ks < 2; ks++) {
            uint32_t af[2][4];
#pragma unroll
            for (int mt = 0; mt < 2; mt++) {
                int ra = wm * 32 + mt * 16 + (lane >> 2);
                int ca = ks * 8 + (lane & 3);
                af[mt][0] = As[ra * APITCH + ca];
                af[mt][1] = As[(ra + 8) * APITCH + ca];
                af[mt][2] = As[ra * APITCH + ca + 4];
                af[mt][3] = As[(ra + 8) * APITCH + ca + 4];
            }
            uint32_t bf[4][2];
#pragma unroll
            for (int nt = 0; nt < 4; nt++) {
                int cn = wn * 32 + nt * 8 + (lane >> 2);
                int rk = ks * 8 + (lane & 3);
                bf[nt][0] = Bs[cn * BPITCH + rk];
                bf[nt][1] = Bs[cn * BPITCH + rk + 4];
            }
#pragma unroll
            for (int mt = 0; mt < 2; mt++)
#pragma unroll
                for (int nt = 0; nt < 4; nt++)
                    mma_tf32_16n8k8(acc[mt][nt], af[mt], bf[nt], acc[mt][nt]);
        }
        __syncthreads();
    }

#pragma unroll
    for (int mt = 0; mt < 2; mt++) {
#pragma unroll
        for (int r2 = 0; r2 < 2; r2++) {
            int m = m0 + wm * 32 + mt * 16 + (lane >> 2) + r2 * 8;
            if (m >= M) continue;
#pragma unroll
            for (int nt = 0; nt < 4; nt++) {
                int c = wn * 32 + nt * 8 + (lane & 3) * 2;
                float v0 = acc[mt][nt][r2 * 2 + 0] + bias[c];
                float v1 = acc[mt][nt][r2 * 2 + 1] + bias[c + 1];
                if (RES) {
                    v0 += res[(size_t)m * 64 + c];
                    v1 += res[(size_t)m * 64 + c + 1];
                }
                out[(size_t)m * 64 + c]     = v0;
                out[(size_t)m * 64 + c + 1] = v1;
            }
        }
    }
}

// ---------------- launcher ----------------
extern "C" void kernel_launch(void* const* d_in, const int* in_sizes, int n_in,
                              void* d_out, int out_size)
{
    const float* pos       = (const float*)d_in[0];
    const float* vel       = (const float*)d_in[1];
    const float* box       = (const float*)d_in[2];
    const float* box_feats = (const float*)d_in[3];
    const int*   ff_q      = (const int*)d_in[4];
    const int*   ff_s      = (const int*)d_in[5];
    const int*   fo_q      = (const int*)d_in[6];
    const int*   fo_s      = (const int*)d_in[7];
    const float* w_cf0     = (const float*)d_in[8];
    const float* w_co0     = (const float*)d_in[9];
    const float* w_d0      = (const float*)d_in[10];
    const float* b_d0      = (const float*)d_in[11];
    const float* w_c1      = (const float*)d_in[12];
    const float* w_d1      = (const float*)d_in[13];
    const float* b_d1      = (const float*)d_in[14];
    const float* w_c2      = (const float*)d_in[15];
    const float* w_d2      = (const float*)d_in[16];
    const float* b_d2      = (const float*)d_in[17];
    const float* w_c3      = (const float*)d_in[18];
    const float* w_d3      = (const float*)d_in[19];
    const float* b_d3      = (const float*)d_in[20];

    int n    = in_sizes[0] / 3;
    int nEff = in_sizes[4];
    int nEfo = in_sizes[6];
    float* out = (float*)d_out;

    float *G, *pos2, *fl, *x, *y, *y2, *ewff, *ewfo, *Wt1, *Wt2;
    int *rows_ff, *rows_fo;
    unsigned char *ecff, *ecfo;
    cudaGetSymbolAddress((void**)&G,       g_G);
    cudaGetSymbolAddress((void**)&pos2,    g_pos2);
    cudaGetSymbolAddress((void**)&fl,      g_fl);
    cudaGetSymbolAddress((void**)&x,       g_x);
    cudaGetSymbolAddress((void**)&y,       g_y);
    cudaGetSymbolAddress((void**)&y2,      g_y2);
    cudaGetSymbolAddress((void**)&Wt1,     g_Wt1);
    cudaGetSymbolAddress((void**)&Wt2,     g_Wt2);
    cudaGetSymbolAddress((void**)&rows_ff, g_rows_ff);
    cudaGetSymbolAddress((void**)&rows_fo, g_rows_fo);
    cudaGetSymbolAddress((void**)&ewff,    g_ew_ff);
    cudaGetSymbolAddress((void**)&ecff,    g_ec_ff);
    cudaGetSymbolAddress((void**)&ewfo,    g_ew_fo);
    cudaGetSymbolAddress((void**)&ecfo,    g_ec_fo);

    int gb  = (n + 63) / 64;
    int gtc = (n + 127) / 128;

    prep_kernel<<<(n + 255) / 256, 256>>>(pos, vel, n, pos2, fl);
    rows_kernel<<<(n + 256) / 256, 256>>>(ff_q, nEff, n, rows_ff);
    rows_kernel<<<(n + 256) / 256, 256>>>(fo_q, nEfo, n, rows_fo);
    edge_geom_kernel<<<(nEff + 255) / 256, 256>>>(pos2, pos2, ff_q, ff_s, nEff, ewff, ecff);
    edge_geom_kernel<<<(nEfo + 255) / 256, 256>>>(pos2, box,  fo_q, fo_s, nEfo, ewfo, ecfo);

    concat_wt_kernel<<<(64 * 6240 + 255) / 256, 256>>>(w_c1, 6144, w_d1, 96, Wt1);
    concat_wt_kernel<<<(64 * 4160 + 255) / 256, 256>>>(w_c2, 4096, w_d2, 64, Wt2);

    // ---- layer 0 (atomic scatter + SIMT gemms) ----
    scatter_kernel<3, false><<<n, 256>>>(box_feats, fo_s, rows_fo, ewfo, ecfo, G);
    gemm_ep_kernel<<<gb, 256>>>(n, 32, 192, G, 192, w_co0,
                                nullptr, 0, 0, 0, nullptr,
                                nullptr, nullptr, 0, x + 0, 96);
    scatter_kernel<4, false><<<n, 256>>>(fl, ff_s, rows_ff, ewff, ecff, G);
    gemm_ep_kernel<<<gb, 256>>>(n, 32, 256, G, 256, w_cf0,
                                nullptr, 0, 0, 0, nullptr,
                                nullptr, nullptr, 0, x + 32, 96);
    gemm_ep_kernel<<<gb, 256>>>(n, 32, 0, nullptr, 0, nullptr,
                                fl, 4, 4, 0, w_d0,
                                b_d0, nullptr, 0, x + 64, 96);

    // ---- layer 1: tensor-core scatter + tensor-core GEMM ----
    mma_scatter_kernel<96, false><<<n, 128>>>(x, ff_s, rows_ff, ewff, ecff, G,
                                              nullptr, nullptr, nullptr,
                                              nullptr, nullptr, nullptr, n);
    mma_gemm_kernel<6144, 96, false><<<gtc, 256>>>(G, x, Wt1, b_d1, nullptr, y, n);

    // ---- layer 2 ----
    mma_scatter_kernel<64, false><<<n, 128>>>(y, ff_s, rows_ff, ewff, ecff, G,
                                              nullptr, nullptr, nullptr,
                                              nullptr, nullptr, nullptr, n);
    mma_gemm_kernel<4096, 64, true><<<gtc, 256>>>(G, y, Wt2, b_d2, y, y2, n);

    // ---- layer 3: fused scatter + reduce + integration ----
    mma_scatter_kernel<64, true><<<n, 128>>>(y2, ff_s, rows_ff, ewff, ecff, nullptr,
                                             w_c3, w_d3, b_d3, pos2, pos, out, n);
}